// round 2
// baseline (speedup 1.0000x reference)
#include <cuda_runtime.h>
#include <math.h>

#define BB 2
#define NN 512
#define DD 256
#define NH 4
#define HD 64
#define MR (BB*NN)   // 1024 rows

// ---------------- scratch (no allocation allowed) ----------------
__device__ float g_q[MR*DD];
__device__ float g_k[MR*DD];
__device__ float g_v[MR*DD];
__device__ float g_a[MR*DD];
__device__ float g_b[MR*DD];
__device__ float g_attn[BB*NH*NN*NN];   // 8 MB
__device__ float g_ctx[MR*DD];

// ---------------- generic 64x64 tiled GEMM body (K=256) ----------------
__device__ __forceinline__ void gemm64_body(
    const float* __restrict__ A,
    const float* __restrict__ W,
    const float* __restrict__ bias,
    float* __restrict__ C,
    int m0, int n0,
    float (*As)[68], float (*Ws)[68])
{
    int tid = threadIdx.x;
    int tx = tid & 15, ty = tid >> 4;
    float acc[4][4] = {};

    for (int k0 = 0; k0 < 256; k0 += 16) {
        __syncthreads();
        // A tile 64x16 -> As[kk][r]
        #pragma unroll
        for (int t = 0; t < 4; t++) {
            int idx = tid + t * 256;
            int r = idx >> 4, c = idx & 15;
            As[c][r] = A[(m0 + r) * 256 + k0 + c];
        }
        // W tile 16x64 -> Ws[kk][c]
        #pragma unroll
        for (int t = 0; t < 4; t++) {
            int idx = tid + t * 256;
            int kk = idx >> 6, c = idx & 63;
            Ws[kk][c] = W[(k0 + kk) * 256 + n0 + c];
        }
        __syncthreads();
        #pragma unroll
        for (int kk = 0; kk < 16; kk++) {
            float ra[4], rb[4];
            #pragma unroll
            for (int i = 0; i < 4; i++) ra[i] = As[kk][ty * 4 + i];
            #pragma unroll
            for (int j = 0; j < 4; j++) rb[j] = Ws[kk][tx * 4 + j];
            #pragma unroll
            for (int i = 0; i < 4; i++)
                #pragma unroll
                for (int j = 0; j < 4; j++)
                    acc[i][j] += ra[i] * rb[j];
        }
    }
    #pragma unroll
    for (int i = 0; i < 4; i++) {
        int m = m0 + ty * 4 + i;
        #pragma unroll
        for (int j = 0; j < 4; j++) {
            int n = n0 + tx * 4 + j;
            float v = acc[i][j];
            if (bias) v += bias[n];
            C[m * 256 + n] = v;
        }
    }
}

// ---------------- K1: input projections (Q,K,V and physics a/b) ----------------
__global__ __launch_bounds__(256) void k_proj(
    const float* __restrict__ x,
    const float* __restrict__ Wq, const float* __restrict__ bq,
    const float* __restrict__ Wk, const float* __restrict__ bk,
    const float* __restrict__ Wv, const float* __restrict__ bv,
    const float* __restrict__ Wp1)
{
    __shared__ float As[16][68];
    __shared__ float Ws[16][68];
    int bn = blockIdx.x;        // 0..19
    int bm = blockIdx.y;        // 0..15
    int seg = bn >> 2;
    int n0 = (bn & 3) * 64;

    const float* W; const float* bias; float* C;
    switch (seg) {
        case 0: W = Wq;             bias = bq;      C = g_q; break;
        case 1: W = Wk;             bias = bk;      C = g_k; break;
        case 2: W = Wv;             bias = bv;      C = g_v; break;
        case 3: W = Wp1;            bias = nullptr; C = g_a; break;
        default: W = Wp1 + 256*256; bias = nullptr; C = g_b; break;
    }
    gemm64_body(x, W, bias, C, bm * 64, n0, As, Ws);
}

// ---------------- K2: fused pair scores (qk + gelu-bias MLP + mask) ----------------
#define TBI 8
#define TBJ 8
__global__ __launch_bounds__(256) void k_scores(
    const int* __restrict__ adj,
    const float* __restrict__ bp1,
    const float* __restrict__ Wp2,
    const float* __restrict__ bp2)
{
    // grid: x = j-split (4 x 128 cols), y = i-tile (64), z = b (2)
    int b = blockIdx.z;
    int i0 = blockIdx.y * TBI;
    int j0base = blockIdx.x * 128;
    int tid = threadIdx.x;
    int lane = tid & 31, w = tid >> 5;

    __shared__ float sA[TBI][256];
    __shared__ float sQ[TBI][256];
    __shared__ float sB[TBJ][256];
    __shared__ float sK[TBJ][256];

    // load A,Q rows for this i-tile (contiguous 2048 floats each)
    const float* aptr = g_a + (b * NN + i0) * 256;
    const float* qptr = g_q + (b * NN + i0) * 256;
    #pragma unroll
    for (int t = 0; t < 8; t++) {
        int idx = tid + t * 256;
        ((float*)sA)[idx] = aptr[idx];
        ((float*)sQ)[idx] = qptr[idx];
    }

    // per-lane constants: channel c = lane + 32k
    float bp1r[8];
    float wp2r[8][4];
    #pragma unroll
    for (int k = 0; k < 8; k++) {
        int c = lane + 32 * k;
        bp1r[k] = bp1[c];
        #pragma unroll
        for (int h = 0; h < 4; h++) wp2r[k][h] = Wp2[c * 4 + h];
    }
    float bp2r0 = bp2[0], bp2r1 = bp2[1], bp2r2 = bp2[2], bp2r3 = bp2[3];
    const float scale = 0.125f;   // 64^-0.5
    const float ISQRT2 = 0.70710678118654752f;

    for (int jc = 0; jc < 128; jc += TBJ) {
        int j0 = j0base + jc;
        __syncthreads();
        const float* bptr = g_b + (b * NN + j0) * 256;
        const float* kptr = g_k + (b * NN + j0) * 256;
        #pragma unroll
        for (int t = 0; t < 8; t++) {
            int idx = tid + t * 256;
            ((float*)sB)[idx] = bptr[idx];
            ((float*)sK)[idx] = kptr[idx];
        }
        __syncthreads();

        int j = j0 + w;   // this warp's key index
        // hoist per-lane key-side values
        float bb[8], kv[8];
        #pragma unroll
        for (int k = 0; k < 8; k++) {
            int c = lane + 32 * k;
            bb[k] = sB[w][c] + bp1r[k];
            kv[k] = sK[w][c];
        }

        for (int il = 0; il < TBI; il++) {
            int i = i0 + il;
            int mval = adj[i * NN + j];
            float* outp = &g_attn[((b * NH) * NN + i) * NN + j];
            if (mval == 0) {
                if (lane < 4) outp[lane * NN * NN] = -1e9f;
                continue;
            }
            float aw0 = 0.f, aw1 = 0.f, aw2 = 0.f, aw3 = 0.f;
            float aq0 = 0.f, aq1 = 0.f, aq2 = 0.f, aq3 = 0.f;
            #pragma unroll
            for (int k = 0; k < 8; k++) {
                int c = lane + 32 * k;
                float t = sA[il][c] + bb[k];
                float g = 0.5f * t * (1.0f + erff(t * ISQRT2));
                aw0 += g * wp2r[k][0];
                aw1 += g * wp2r[k][1];
                aw2 += g * wp2r[k][2];
                aw3 += g * wp2r[k][3];
                float qk = sQ[il][c] * kv[k];
                // head = k>>1 (channels [32k,32k+32) lie in head k/2)
                if ((k >> 1) == 0) aq0 += qk;
                else if ((k >> 1) == 1) aq1 += qk;
                else if ((k >> 1) == 2) aq2 += qk;
                else aq3 += qk;
            }
            float s0 = aq0 * scale + aw0 + bp2r0;
            float s1 = aq1 * scale + aw1 + bp2r1;
            float s2 = aq2 * scale + aw2 + bp2r2;
            float s3 = aq3 * scale + aw3 + bp2r3;
            #pragma unroll
            for (int off = 16; off; off >>= 1) {
                s0 += __shfl_xor_sync(0xffffffffu, s0, off);
                s1 += __shfl_xor_sync(0xffffffffu, s1, off);
                s2 += __shfl_xor_sync(0xffffffffu, s2, off);
                s3 += __shfl_xor_sync(0xffffffffu, s3, off);
            }
            if (lane < 4) {
                float sv = (lane == 0) ? s0 : (lane == 1) ? s1 : (lane == 2) ? s2 : s3;
                outp[lane * NN * NN] = sv;
            }
        }
    }
}

// ---------------- K3: softmax over j (warp per row) ----------------
__global__ __launch_bounds__(256) void k_softmax()
{
    int row = blockIdx.x * 8 + (threadIdx.x >> 5);   // B*H*N = 4096 rows
    int lane = threadIdx.x & 31;
    float* p = g_attn + (long)row * NN;

    float4 v[4];
    float mx = -3.4e38f;
    #pragma unroll
    for (int t = 0; t < 4; t++) {
        v[t] = *(const float4*)&p[lane * 4 + t * 128];
        mx = fmaxf(mx, fmaxf(fmaxf(v[t].x, v[t].y), fmaxf(v[t].z, v[t].w)));
    }
    #pragma unroll
    for (int off = 16; off; off >>= 1)
        mx = fmaxf(mx, __shfl_xor_sync(0xffffffffu, mx, off));

    float sum = 0.f;
    #pragma unroll
    for (int t = 0; t < 4; t++) {
        v[t].x = expf(v[t].x - mx);
        v[t].y = expf(v[t].y - mx);
        v[t].z = expf(v[t].z - mx);
        v[t].w = expf(v[t].w - mx);
        sum += v[t].x + v[t].y + v[t].z + v[t].w;
    }
    #pragma unroll
    for (int off = 16; off; off >>= 1)
        sum += __shfl_xor_sync(0xffffffffu, sum, off);
    float inv = 1.0f / sum;
    #pragma unroll
    for (int t = 0; t < 4; t++) {
        v[t].x *= inv; v[t].y *= inv; v[t].z *= inv; v[t].w *= inv;
        *(float4*)&p[lane * 4 + t * 128] = v[t];
    }
}

// ---------------- K4: out = attn @ v  -> ctx[b,i,h*64+d] ----------------
#define TTI 16
__global__ __launch_bounds__(256) void k_av()
{
    int b = blockIdx.z, h = blockIdx.y;
    int i_base = blockIdx.x * TTI;
    int tid = threadIdx.x;

    __shared__ float sP[TTI][512];   // 32 KB
    __shared__ float sV[32][64];     //  8 KB

    const float* attn = g_attn + (((long)(b * NH + h)) * NN + i_base) * NN;
    #pragma unroll
    for (int t = 0; t < 8; t++)
        ((float4*)sP)[tid + t * 256] = ((const float4*)attn)[tid + t * 256];

    int d0 = (tid & 15) * 4;
    int i  = tid >> 4;
    float acc0 = 0.f, acc1 = 0.f, acc2 = 0.f, acc3 = 0.f;

    for (int j0 = 0; j0 < 512; j0 += 32) {
        __syncthreads();
        #pragma unroll
        for (int t = 0; t < 8; t++) {
            int idx = tid + t * 256;
            int r = idx >> 6, c = idx & 63;
            sV[r][c] = g_v[(b * NN + j0 + r) * 256 + h * 64 + c];
        }
        __syncthreads();
        #pragma unroll 8
        for (int j = 0; j < 32; j++) {
            float pv = sP[i][j0 + j];
            float4 vv = *(const float4*)&sV[j][d0];
            acc0 += pv * vv.x;
            acc1 += pv * vv.y;
            acc2 += pv * vv.z;
            acc3 += pv * vv.w;
        }
    }
    float4 r4 = make_float4(acc0, acc1, acc2, acc3);
    *(float4*)&g_ctx[(b * NN + i_base + i) * 256 + h * 64 + d0] = r4;
}

// ---------------- K5: final projection ----------------
__global__ __launch_bounds__(256) void k_out(
    const float* __restrict__ Wo, const float* __restrict__ bo,
    float* __restrict__ out)
{
    __shared__ float As[16][68];
    __shared__ float Ws[16][68];
    gemm64_body(g_ctx, Wo, bo, out, blockIdx.y * 64, blockIdx.x * 64, As, Ws);
}

// ---------------- launch ----------------
extern "C" void kernel_launch(void* const* d_in, const int* in_sizes, int n_in,
                              void* d_out, int out_size)
{
    const float* x   = (const float*)d_in[0];
    const int*   adj = (const int*)  d_in[1];
    const float* Wq  = (const float*)d_in[2];
    const float* bq  = (const float*)d_in[3];
    const float* Wk  = (const float*)d_in[4];
    const float* bk  = (const float*)d_in[5];
    const float* Wv  = (const float*)d_in[6];
    const float* bv  = (const float*)d_in[7];
    const float* Wo  = (const float*)d_in[8];
    const float* bo  = (const float*)d_in[9];
    const float* Wp1 = (const float*)d_in[10];
    const float* bp1 = (const float*)d_in[11];
    const float* Wp2 = (const float*)d_in[12];
    const float* bp2 = (const float*)d_in[13];
    float* out = (float*)d_out;

    dim3 g1(20, 16);
    k_proj<<<g1, 256>>>(x, Wq, bq, Wk, bk, Wv, bv, Wp1);

    dim3 g2(4, 64, 2);
    k_scores<<<g2, 256>>>(adj, bp1, Wp2, bp2);

    k_softmax<<<512, 256>>>();

    dim3 g4(32, 4, 2);
    k_av<<<g4, 256>>>();

    dim3 g5(4, 16);
    k_out<<<g5, 256>>>(Wo, bo, out);
}

// round 3
// speedup vs baseline: 1.1905x; 1.1905x over previous
#include <cuda_runtime.h>
#include <math.h>

typedef unsigned long long u64;
#define BB 2
#define NN 512
#define DD 256
#define NH 4
#define MR (BB*NN)

__device__ float g_q[MR*DD];
__device__ float g_k[MR*DD];
__device__ float g_v[MR*DD];
__device__ float g_a[MR*DD];
__device__ float g_b[MR*DD];
__device__ float g_attn[(size_t)BB*NH*NN*NN];
__device__ float g_ctx[MR*DD];

struct GCoef { float c[17]; };

__device__ __forceinline__ u64 pk(float lo, float hi) {
    u64 r; asm("mov.b64 %0,{%1,%2};" : "=l"(r) : "f"(lo), "f"(hi)); return r;
}
__device__ __forceinline__ void upk(u64 v, float& lo, float& hi) {
    asm("mov.b64 {%0,%1},%2;" : "=f"(lo), "=f"(hi) : "l"(v));
}
__device__ __forceinline__ u64 f2add(u64 a, u64 b) {
    u64 d; asm("add.rn.f32x2 %0,%1,%2;" : "=l"(d) : "l"(a), "l"(b)); return d;
}
__device__ __forceinline__ u64 f2fma(u64 a, u64 b, u64 c) {
    u64 d; asm("fma.rn.f32x2 %0,%1,%2,%3;" : "=l"(d) : "l"(a), "l"(b), "l"(c)); return d;
}

// ---------------- 64x64 tiled GEMM body (K=256) ----------------
__device__ __forceinline__ void gemm64_body(
    const float* __restrict__ A, const float* __restrict__ W,
    const float* __restrict__ bias, float* __restrict__ C,
    int m0, int n0, float (*As)[68], float (*Ws)[68])
{
    int tid = threadIdx.x, tx = tid & 15, ty = tid >> 4;
    float acc[4][4] = {};
    for (int k0 = 0; k0 < 256; k0 += 16) {
        __syncthreads();
        #pragma unroll
        for (int t = 0; t < 4; t++) {
            int idx = tid + t * 256;
            As[idx & 15][idx >> 4] = A[(m0 + (idx >> 4)) * 256 + k0 + (idx & 15)];
        }
        #pragma unroll
        for (int t = 0; t < 4; t++) {
            int idx = tid + t * 256;
            Ws[idx >> 6][idx & 63] = W[(k0 + (idx >> 6)) * 256 + n0 + (idx & 63)];
        }
        __syncthreads();
        #pragma unroll
        for (int kk = 0; kk < 16; kk++) {
            float ra[4], rb[4];
            #pragma unroll
            for (int i = 0; i < 4; i++) ra[i] = As[kk][ty * 4 + i];
            #pragma unroll
            for (int j = 0; j < 4; j++) rb[j] = Ws[kk][tx * 4 + j];
            #pragma unroll
            for (int i = 0; i < 4; i++)
                #pragma unroll
                for (int j = 0; j < 4; j++) acc[i][j] += ra[i] * rb[j];
        }
    }
    #pragma unroll
    for (int i = 0; i < 4; i++)
        #pragma unroll
        for (int j = 0; j < 4; j++) {
            int n = n0 + tx * 4 + j;
            float v = acc[i][j];
            if (bias) v += bias[n];
            C[(m0 + ty * 4 + i) * 256 + n] = v;
        }
}

__global__ __launch_bounds__(256) void k_proj(
    const float* __restrict__ x,
    const float* __restrict__ Wq, const float* __restrict__ bq,
    const float* __restrict__ Wk, const float* __restrict__ bk,
    const float* __restrict__ Wv, const float* __restrict__ bv,
    const float* __restrict__ Wp1, const float* __restrict__ bp1)
{
    __shared__ float As[16][68], Ws[16][68];
    int bn = blockIdx.x, bm = blockIdx.y;
    int seg = bn >> 2, n0 = (bn & 3) * 64;
    const float* W; const float* bias; float* C;
    switch (seg) {
        case 0: W = Wq; bias = bq; C = g_q; break;
        case 1: W = Wk; bias = bk; C = g_k; break;
        case 2: W = Wv; bias = bv; C = g_v; break;
        case 3: W = Wp1; bias = nullptr; C = g_a; break;
        default: W = Wp1 + 256*256; bias = bp1; C = g_b; break;  // fold bp1
    }
    gemm64_body(x, W, bias, C, bm * 64, n0, As, Ws);
}

// ---------------- K2: fused pair scores, packed f32x2 ----------------
__global__ __launch_bounds__(256) void k_scores(
    const int* __restrict__ adj, const float* __restrict__ Wp2,
    const float* __restrict__ bp2, GCoef co)
{
    int b = blockIdx.z, i0 = blockIdx.y * 8, j0base = blockIdx.x * 128;
    int tid = threadIdx.x, lane = tid & 31, w = tid >> 5;
    int h = lane >> 3;

    __shared__ float sA[8][256], sQ[8][256], sB[8][256], sK[8][256];

    u64 C[17];
    #pragma unroll
    for (int kk = 0; kk < 17; kk++) C[kk] = pk(co.c[kk], co.c[kk]);
    const u64 K3 = pk(1.0f/3.0f, 1.0f/3.0f);
    const u64 KM1 = pk(-1.0f, -1.0f);
    const u64 KABS = 0x7FFFFFFF7FFFFFFFull;

    u64 w2[4][4];
    {
        int cb = lane * 8;
        #pragma unroll
        for (int p = 0; p < 4; p++) {
            float4 wa = *(const float4*)&Wp2[(cb + 2*p) * 4];
            float4 wb = *(const float4*)&Wp2[(cb + 2*p + 1) * 4];
            w2[p][0] = pk(0.5f*wa.x, 0.5f*wb.x);
            w2[p][1] = pk(0.5f*wa.y, 0.5f*wb.y);
            w2[p][2] = pk(0.5f*wa.z, 0.5f*wb.z);
            w2[p][3] = pk(0.5f*wa.w, 0.5f*wb.w);
        }
    }
    float myb = bp2[h];

    const float* aptr = g_a + (b * NN + i0) * 256;
    const float* qptr = g_q + (b * NN + i0) * 256;
    #pragma unroll
    for (int t = 0; t < 2; t++) {
        int idx = tid + t * 256;
        ((float4*)sA)[idx] = ((const float4*)aptr)[idx];
        ((float4*)sQ)[idx] = ((const float4*)qptr)[idx];
    }

    for (int jc = 0; jc < 128; jc += 8) {
        int j0 = j0base + jc;
        __syncthreads();
        const float* bptr = g_b + (b * NN + j0) * 256;
        const float* kptr = g_k + (b * NN + j0) * 256;
        #pragma unroll
        for (int t = 0; t < 2; t++) {
            int idx = tid + t * 256;
            ((float4*)sB)[idx] = ((const float4*)bptr)[idx];
            ((float4*)sK)[idx] = ((const float4*)kptr)[idx];
        }
        __syncthreads();

        int j = j0 + w;
        u64 bbp[4], kvp[4];
        {
            float4 b0 = *(const float4*)&sB[w][lane*8];
            float4 b1 = *(const float4*)&sB[w][lane*8+4];
            float4 k0 = *(const float4*)&sK[w][lane*8];
            float4 k1 = *(const float4*)&sK[w][lane*8+4];
            bbp[0]=pk(b0.x,b0.y); bbp[1]=pk(b0.z,b0.w);
            bbp[2]=pk(b1.x,b1.y); bbp[3]=pk(b1.z,b1.w);
            kvp[0]=pk(k0.x,k0.y); kvp[1]=pk(k0.z,k0.w);
            kvp[2]=pk(k1.x,k1.y); kvp[3]=pk(k1.z,k1.w);
        }

        #pragma unroll
        for (int il = 0; il < 8; il++) {
            int i = i0 + il;
            int mval = adj[i * NN + j];
            float* outp = &g_attn[((size_t)(b * NH) * NN + i) * NN + j];
            if (mval == 0) {
                if ((lane & 7) == 0) outp[(size_t)h * NN * NN] = -1e9f;
                continue;
            }
            float4 a0 = *(const float4*)&sA[il][lane*8];
            float4 a1 = *(const float4*)&sA[il][lane*8+4];
            float4 q0 = *(const float4*)&sQ[il][lane*8];
            float4 q1 = *(const float4*)&sQ[il][lane*8+4];
            u64 aA[4] = {pk(a0.x,a0.y), pk(a0.z,a0.w), pk(a1.x,a1.y), pk(a1.z,a1.w)};
            u64 qA[4] = {pk(q0.x,q0.y), pk(q0.z,q0.w), pk(q1.x,q1.y), pk(q1.z,q1.w)};

            u64 aw0=0, aw1=0, aw2=0, aw3=0, qk=0;
            #pragma unroll
            for (int p = 0; p < 4; p++) {
                u64 t = f2add(aA[p], bbp[p]);
                u64 m = t & KABS;
                u64 wv = f2fma(m, K3, KM1);
                u64 S = C[16];
                #pragma unroll
                for (int kk = 15; kk >= 0; kk--) S = f2fma(S, wv, C[kk]);
                // gelu*2 = (t+m) + S(m)   (S poly already = -2*0.5*m*erfc(m/sqrt2))
                u64 G = f2add(f2add(t, m), S);
                aw0 = f2fma(G, w2[p][0], aw0);
                aw1 = f2fma(G, w2[p][1], aw1);
                aw2 = f2fma(G, w2[p][2], aw2);
                aw3 = f2fma(G, w2[p][3], aw3);
                qk  = f2fma(qA[p], kvp[p], qk);
            }
            float r0,r1,r2,r3,x0,x1,qx,qy;
            upk(aw0,r0,x0); r0+=x0;
            upk(aw1,r1,x1); r1+=x1;
            upk(aw2,r2,x0); r2+=x0;
            upk(aw3,r3,x1); r3+=x1;
            upk(qk,qx,qy);
            float qs = (qx+qy)*0.125f;
            if (h==0) r0+=qs; else if (h==1) r1+=qs; else if (h==2) r2+=qs; else r3+=qs;

            r0 += __shfl_xor_sync(~0u, r0, 16);
            r1 += __shfl_xor_sync(~0u, r1, 16);
            r2 += __shfl_xor_sync(~0u, r2, 16);
            r3 += __shfl_xor_sync(~0u, r3, 16);
            r0 += __shfl_xor_sync(~0u, r0, 8);
            r1 += __shfl_xor_sync(~0u, r1, 8);
            r2 += __shfl_xor_sync(~0u, r2, 8);
            r3 += __shfl_xor_sync(~0u, r3, 8);
            float v = (h==0)?r0:(h==1)?r1:(h==2)?r2:r3;
            v += __shfl_xor_sync(~0u, v, 4);
            v += __shfl_xor_sync(~0u, v, 2);
            v += __shfl_xor_sync(~0u, v, 1);
            if ((lane & 7) == 0) outp[(size_t)h * NN * NN] = v + myb;
        }
    }
}

// ---------------- fast exp: 2^(x*log2e), no MUFU ----------------
__device__ __forceinline__ float fexp(float x) {
    x = fmaxf(x, -87.0f);
    float y = x * 1.4426950408889634f;
    float f = floorf(y);
    float r = y - f;
    float p = 1.5403530e-4f;
    p = fmaf(p, r, 1.3333558e-3f);
    p = fmaf(p, r, 9.6181291e-3f);
    p = fmaf(p, r, 5.5504109e-2f);
    p = fmaf(p, r, 2.4022651e-1f);
    p = fmaf(p, r, 6.9314718e-1f);
    p = fmaf(p, r, 1.0f);
    return __int_as_float(__float_as_int(p) + (((int)f) << 23));
}

// ---------------- K3: fused softmax + attn@v ----------------
#define TTI 16
__global__ __launch_bounds__(256) void k_av()
{
    int b = blockIdx.z, h = blockIdx.y, i0 = blockIdx.x * TTI;
    int tid = threadIdx.x, w = tid >> 5, lane = tid & 31;

    __shared__ float sP[TTI][516];   // padded: row stride 2064B (16B aligned)
    __shared__ float sV[32][64];
    __shared__ float sInv[TTI];

    // phase A: softmax (unnormalized exp) — warp w handles rows w and w+8
    #pragma unroll
    for (int rr = w; rr < TTI; rr += 8) {
        const float* arow = g_attn + (((size_t)(b*NH+h))*NN + (i0+rr))*NN;
        float4 vv[4];
        float mx = -3.4e38f;
        #pragma unroll
        for (int t = 0; t < 4; t++) {
            vv[t] = ((const float4*)arow)[lane + 32*t];
            mx = fmaxf(mx, fmaxf(fmaxf(vv[t].x,vv[t].y), fmaxf(vv[t].z,vv[t].w)));
        }
        #pragma unroll
        for (int o = 16; o; o >>= 1) mx = fmaxf(mx, __shfl_xor_sync(~0u, mx, o));
        float s = 0.f;
        #pragma unroll
        for (int t = 0; t < 4; t++) {
            vv[t].x = fexp(vv[t].x - mx); vv[t].y = fexp(vv[t].y - mx);
            vv[t].z = fexp(vv[t].z - mx); vv[t].w = fexp(vv[t].w - mx);
            s += vv[t].x + vv[t].y + vv[t].z + vv[t].w;
            *(float4*)&sP[rr][lane*4 + t*128] = vv[t];
        }
        #pragma unroll
        for (int o = 16; o; o >>= 1) s += __shfl_xor_sync(~0u, s, o);
        if (lane == 0) sInv[rr] = 1.0f / s;
    }

    int d0 = (tid & 15) * 4;
    int i  = tid >> 4;
    float a0=0.f, a1=0.f, a2=0.f, a3=0.f;

    for (int j0 = 0; j0 < 512; j0 += 32) {
        __syncthreads();
        #pragma unroll
        for (int t = 0; t < 8; t++) {
            int idx = tid + t * 256;
            sV[idx >> 6][idx & 63] = g_v[(b*NN + j0 + (idx>>6))*256 + h*64 + (idx & 63)];
        }
        __syncthreads();
        #pragma unroll 8
        for (int j = 0; j < 32; j++) {
            float pv = sP[i][j0 + j];
            float4 vv = *(const float4*)&sV[j][d0];
            a0 = fmaf(pv, vv.x, a0); a1 = fmaf(pv, vv.y, a1);
            a2 = fmaf(pv, vv.z, a2); a3 = fmaf(pv, vv.w, a3);
        }
    }
    float inv = sInv[i];
    float4 r4 = make_float4(a0*inv, a1*inv, a2*inv, a3*inv);
    *(float4*)&g_ctx[(b*NN + i0 + i)*256 + h*64 + d0] = r4;
}

__global__ __launch_bounds__(256) void k_out(
    const float* __restrict__ Wo, const float* __restrict__ bo,
    float* __restrict__ out)
{
    __shared__ float As[16][68], Ws[16][68];
    gemm64_body(g_ctx, Wo, bo, out, blockIdx.y * 64, blockIdx.x * 64, As, Ws);
}

// ---------------- host: Chebyshev fit of -m*erfc(m/sqrt2) on m in [0,6] ----------------
static GCoef fit_gelu_poly() {
    const int DEG = 16, M = 64;
    double cc[DEG+1];
    double fv[M];
    for (int j = 0; j < M; j++) {
        double x = cos(M_PI * (j + 0.5) / M);
        double m = 3.0 * (x + 1.0);
        fv[j] = -m * erfc(m * 0.7071067811865476);
    }
    for (int k = 0; k <= DEG; k++) {
        double s = 0;
        for (int j = 0; j < M; j++) s += fv[j] * cos(k * M_PI * (j + 0.5) / M);
        cc[k] = s * ((k == 0 ? 1.0 : 2.0) / M);
    }
    // Chebyshev -> monomial in w
    double mono[DEG+1] = {0}, Tm2[DEG+1] = {0}, Tm1[DEG+1] = {0}, Tk[DEG+1];
    Tm2[0] = 1.0; Tm1[1] = 1.0;
    mono[0] += cc[0];
    mono[1] += cc[1];
    for (int k = 2; k <= DEG; k++) {
        for (int i = 0; i <= DEG; i++) Tk[i] = -Tm2[i] + 2.0 * (i > 0 ? Tm1[i-1] : 0.0);
        for (int i = 0; i <= DEG; i++) mono[i] += cc[k] * Tk[i];
        for (int i = 0; i <= DEG; i++) { Tm2[i] = Tm1[i]; Tm1[i] = Tk[i]; }
    }
    GCoef g;
    for (int i = 0; i <= DEG; i++) g.c[i] = (float)mono[i];
    return g;
}

extern "C" void kernel_launch(void* const* d_in, const int* in_sizes, int n_in,
                              void* d_out, int out_size)
{
    const float* x   = (const float*)d_in[0];
    const int*   adj = (const int*)  d_in[1];
    const float* Wq  = (const float*)d_in[2];
    const float* bq  = (const float*)d_in[3];
    const float* Wk  = (const float*)d_in[4];
    const float* bk  = (const float*)d_in[5];
    const float* Wv  = (const float*)d_in[6];
    const float* bv  = (const float*)d_in[7];
    const float* Wo  = (const float*)d_in[8];
    const float* bo  = (const float*)d_in[9];
    const float* Wp1 = (const float*)d_in[10];
    const float* bp1 = (const float*)d_in[11];
    const float* Wp2 = (const float*)d_in[12];
    const float* bp2 = (const float*)d_in[13];
    float* out = (float*)d_out;

    GCoef co = fit_gelu_poly();

    dim3 g1(20, 16);
    k_proj<<<g1, 256>>>(x, Wq, bq, Wk, bk, Wv, bv, Wp1, bp1);

    dim3 g2(4, 64, 2);
    k_scores<<<g2, 256>>>(adj, Wp2, bp2, co);

    dim3 g4(32, 4, 2);
    k_av<<<g4, 256>>>();

    dim3 g5(4, 16);
    k_out<<<g5, 256>>>(Wo, bo, out);
}

// round 4
// speedup vs baseline: 1.4190x; 1.1919x over previous
#include <cuda_runtime.h>
#include <math.h>

typedef unsigned long long u64;
#define BB 2
#define NN 512
#define DD 256
#define NH 4
#define MR (BB*NN)

__device__ float g_q[MR*DD];
__device__ float g_k[MR*DD];
__device__ float g_v[MR*DD];
__device__ float g_a[MR*DD];
__device__ float g_b[MR*DD];
__device__ float g_attn[(size_t)BB*NH*NN*NN];
__device__ float g_ctx[MR*DD];

struct GCoef { float c[13]; };

__device__ __forceinline__ u64 pk(float lo, float hi) {
    u64 r; asm("mov.b64 %0,{%1,%2};" : "=l"(r) : "f"(lo), "f"(hi)); return r;
}
__device__ __forceinline__ void upk(u64 v, float& lo, float& hi) {
    asm("mov.b64 {%0,%1},%2;" : "=f"(lo), "=f"(hi) : "l"(v));
}
__device__ __forceinline__ u64 f2add(u64 a, u64 b) {
    u64 d; asm("add.rn.f32x2 %0,%1,%2;" : "=l"(d) : "l"(a), "l"(b)); return d;
}
__device__ __forceinline__ u64 f2fma(u64 a, u64 b, u64 c) {
    u64 d; asm("fma.rn.f32x2 %0,%1,%2,%3;" : "=l"(d) : "l"(a), "l"(b), "l"(c)); return d;
}

// ---------------- 32x64 tiled GEMM body (K=256), packed f32x2 acc ----------------
__device__ __forceinline__ void gemm32x64(
    const float* __restrict__ A, const float* __restrict__ W,
    const float* __restrict__ bias, float* __restrict__ C,
    int m0, int n0)
{
    __shared__ __align__(16) float As[16][36];
    __shared__ __align__(16) float Ws[16][68];
    int tid = threadIdx.x, tx = tid & 15, ty = tid >> 4;
    u64 acc[2][2] = {{0ull,0ull},{0ull,0ull}};

    for (int k0 = 0; k0 < 256; k0 += 16) {
        __syncthreads();
        #pragma unroll
        for (int t = 0; t < 2; t++) {
            int idx = tid + t * 256;
            As[idx & 15][idx >> 4] = A[(m0 + (idx >> 4)) * 256 + k0 + (idx & 15)];
        }
        #pragma unroll
        for (int t = 0; t < 4; t++) {
            int idx = tid + t * 256;
            Ws[idx >> 6][idx & 63] = W[(k0 + (idx >> 6)) * 256 + n0 + (idx & 63)];
        }
        __syncthreads();
        #pragma unroll
        for (int kk = 0; kk < 16; kk++) {
            float2 ra = *(const float2*)&As[kk][ty * 2];
            ulonglong2 wv = *(const ulonglong2*)&Ws[kk][tx * 4];
            u64 r0 = pk(ra.x, ra.x), r1 = pk(ra.y, ra.y);
            acc[0][0] = f2fma(r0, wv.x, acc[0][0]);
            acc[0][1] = f2fma(r0, wv.y, acc[0][1]);
            acc[1][0] = f2fma(r1, wv.x, acc[1][0]);
            acc[1][1] = f2fma(r1, wv.y, acc[1][1]);
        }
    }
    int n = n0 + tx * 4;
    float b0 = 0.f, b1 = 0.f, b2 = 0.f, b3 = 0.f;
    if (bias) { b0 = bias[n]; b1 = bias[n+1]; b2 = bias[n+2]; b3 = bias[n+3]; }
    #pragma unroll
    for (int i = 0; i < 2; i++) {
        float o0,o1,o2,o3;
        upk(acc[i][0], o0, o1); upk(acc[i][1], o2, o3);
        *(float4*)&C[(m0 + ty*2 + i) * 256 + n] =
            make_float4(o0 + b0, o1 + b1, o2 + b2, o3 + b3);
    }
}

__global__ __launch_bounds__(256) void k_proj(
    const float* __restrict__ x,
    const float* __restrict__ Wq, const float* __restrict__ bq,
    const float* __restrict__ Wk, const float* __restrict__ bk,
    const float* __restrict__ Wv, const float* __restrict__ bv,
    const float* __restrict__ Wp1, const float* __restrict__ bp1)
{
    int bn = blockIdx.x;
    int seg = bn >> 2, n0 = (bn & 3) * 64;
    const float* W; const float* bias; float* C;
    switch (seg) {
        case 0: W = Wq; bias = bq; C = g_q; break;
        case 1: W = Wk; bias = bk; C = g_k; break;
        case 2: W = Wv; bias = bv; C = g_v; break;
        case 3: W = Wp1; bias = nullptr; C = g_a; break;
        default: W = Wp1 + 256*256; bias = bp1; C = g_b; break;  // bp1 folded
    }
    gemm32x64(x, W, bias, C, blockIdx.y * 32, n0);
}

// ---------------- K2: fused pair scores ----------------
__global__ __launch_bounds__(256, 2) void k_scores(
    const int* __restrict__ adj, const float* __restrict__ Wp2,
    const float* __restrict__ bp2, GCoef co)
{
    int b = blockIdx.z, i0 = blockIdx.y * 8, j0base = blockIdx.x * 128;
    int tid = threadIdx.x, lane = tid & 31, w = tid >> 5;
    int h = lane >> 3;

    __shared__ __align__(16) float sA[8][256], sQ[8][256], sB[8][256], sK[8][256];
    __shared__ int sM[8][128];

    u64 C[13];
    #pragma unroll
    for (int kk = 0; kk < 13; kk++) C[kk] = pk(co.c[kk], co.c[kk]);
    const u64 K3 = pk(1.0f/3.0f, 1.0f/3.0f);
    const u64 KM1 = pk(-1.0f, -1.0f);
    const u64 KABS = 0x7FFFFFFF7FFFFFFFull;

    u64 w2[4][4];
    {
        int cb = lane * 8;
        #pragma unroll
        for (int p = 0; p < 4; p++) {
            float4 wa = *(const float4*)&Wp2[(cb + 2*p) * 4];
            float4 wb = *(const float4*)&Wp2[(cb + 2*p + 1) * 4];
            w2[p][0] = pk(0.5f*wa.x, 0.5f*wb.x);
            w2[p][1] = pk(0.5f*wa.y, 0.5f*wb.y);
            w2[p][2] = pk(0.5f*wa.z, 0.5f*wb.z);
            w2[p][3] = pk(0.5f*wa.w, 0.5f*wb.w);
        }
    }
    float myb = bp2[h];

    const float* aptr = g_a + (b * NN + i0) * 256;
    const float* qptr = g_q + (b * NN + i0) * 256;
    #pragma unroll
    for (int t = 0; t < 2; t++) {
        int idx = tid + t * 256;
        ((float4*)sA)[idx] = ((const float4*)aptr)[idx];
        ((float4*)sQ)[idx] = ((const float4*)qptr)[idx];
    }
    // adjacency tile to smem (kills per-iter global latency)
    #pragma unroll
    for (int t = 0; t < 4; t++) {
        int idx = tid + t * 256;
        sM[idx >> 7][idx & 127] = adj[(i0 + (idx >> 7)) * NN + j0base + (idx & 127)];
    }

    for (int jc = 0; jc < 128; jc += 8) {
        int j0 = j0base + jc;
        __syncthreads();
        const float* bptr = g_b + (b * NN + j0) * 256;
        const float* kptr = g_k + (b * NN + j0) * 256;
        #pragma unroll
        for (int t = 0; t < 2; t++) {
            int idx = tid + t * 256;
            ((float4*)sB)[idx] = ((const float4*)bptr)[idx];
            ((float4*)sK)[idx] = ((const float4*)kptr)[idx];
        }
        __syncthreads();

        int j = j0 + w;
        u64 bbp[4], kvp[4];
        {
            ulonglong2 x0 = *(const ulonglong2*)&sB[w][lane*8];
            ulonglong2 x1 = *(const ulonglong2*)&sB[w][lane*8+4];
            bbp[0]=x0.x; bbp[1]=x0.y; bbp[2]=x1.x; bbp[3]=x1.y;
            ulonglong2 y0 = *(const ulonglong2*)&sK[w][lane*8];
            ulonglong2 y1 = *(const ulonglong2*)&sK[w][lane*8+4];
            kvp[0]=y0.x; kvp[1]=y0.y; kvp[2]=y1.x; kvp[3]=y1.y;
        }

        #pragma unroll
        for (int il = 0; il < 8; il++) {
            int mval = sM[il][jc + w];
            float* outp = &g_attn[((size_t)(b * NH) * NN + (i0+il)) * NN + j];
            if (mval == 0) {
                if ((lane & 7) == 0) outp[(size_t)h * NN * NN] = -1e9f;
                continue;
            }
            u64 aA[4], qA[4];
            {
                ulonglong2 x0 = *(const ulonglong2*)&sA[il][lane*8];
                ulonglong2 x1 = *(const ulonglong2*)&sA[il][lane*8+4];
                aA[0]=x0.x; aA[1]=x0.y; aA[2]=x1.x; aA[3]=x1.y;
                ulonglong2 y0 = *(const ulonglong2*)&sQ[il][lane*8];
                ulonglong2 y1 = *(const ulonglong2*)&sQ[il][lane*8+4];
                qA[0]=y0.x; qA[1]=y0.y; qA[2]=y1.x; qA[3]=y1.y;
            }

            u64 aw0=0, aw1=0, aw2=0, aw3=0, qk=0;
            #pragma unroll
            for (int p = 0; p < 4; p++) {
                u64 t = f2add(aA[p], bbp[p]);
                u64 m = t & KABS;
                u64 wv = f2fma(m, K3, KM1);
                u64 S = C[12];
                #pragma unroll
                for (int kk = 11; kk >= 0; kk--) S = f2fma(S, wv, C[kk]);
                u64 G = f2add(f2add(t, m), S);   // 2*gelu
                aw0 = f2fma(G, w2[p][0], aw0);
                aw1 = f2fma(G, w2[p][1], aw1);
                aw2 = f2fma(G, w2[p][2], aw2);
                aw3 = f2fma(G, w2[p][3], aw3);
                qk  = f2fma(qA[p], kvp[p], qk);
            }
            float r0,r1,r2,r3,x0,x1,qx,qy;
            upk(aw0,r0,x0); r0+=x0;
            upk(aw1,r1,x1); r1+=x1;
            upk(aw2,r2,x0); r2+=x0;
            upk(aw3,r3,x1); r3+=x1;
            upk(qk,qx,qy);
            float qs = (qx+qy)*0.125f;
            if (h==0) r0+=qs; else if (h==1) r1+=qs; else if (h==2) r2+=qs; else r3+=qs;

            r0 += __shfl_xor_sync(~0u, r0, 16);
            r1 += __shfl_xor_sync(~0u, r1, 16);
            r2 += __shfl_xor_sync(~0u, r2, 16);
            r3 += __shfl_xor_sync(~0u, r3, 16);
            r0 += __shfl_xor_sync(~0u, r0, 8);
            r1 += __shfl_xor_sync(~0u, r1, 8);
            r2 += __shfl_xor_sync(~0u, r2, 8);
            r3 += __shfl_xor_sync(~0u, r3, 8);
            float v = (h==0)?r0:(h==1)?r1:(h==2)?r2:r3;
            v += __shfl_xor_sync(~0u, v, 4);
            v += __shfl_xor_sync(~0u, v, 2);
            v += __shfl_xor_sync(~0u, v, 1);
            if ((lane & 7) == 0) outp[(size_t)h * NN * NN] = v + myb;
        }
    }
}

// ---------------- fast exp (no MUFU) ----------------
__device__ __forceinline__ float fexp(float x) {
    x = fmaxf(x, -87.0f);
    float y = x * 1.4426950408889634f;
    float f = floorf(y);
    float r = y - f;
    float p = 1.5403530e-4f;
    p = fmaf(p, r, 1.3333558e-3f);
    p = fmaf(p, r, 9.6181291e-3f);
    p = fmaf(p, r, 5.5504109e-2f);
    p = fmaf(p, r, 2.4022651e-1f);
    p = fmaf(p, r, 6.9314718e-1f);
    p = fmaf(p, r, 1.0f);
    return __int_as_float(__float_as_int(p) + (((int)f) << 23));
}

// ---------------- K3: fused softmax + attn@v (register-blocked) ----------------
__global__ __launch_bounds__(256) void k_av()
{
    int b = blockIdx.z, h = blockIdx.y, i0 = blockIdx.x * 8;
    int tid = threadIdx.x, w = tid >> 5, lane = tid & 31;

    __shared__ __align__(16) float sP[8][512];     // 16 KB
    __shared__ __align__(16) float sRed[8][8][64]; // 16 KB
    __shared__ float sInv[8];

    // phase A: warp w computes unnormalized softmax of row i0+w
    {
        const float* arow = g_attn + (((size_t)(b*NH+h))*NN + (i0+w))*NN;
        float4 vv[4];
        float mx = -3.4e38f;
        #pragma unroll
        for (int t = 0; t < 4; t++) {
            vv[t] = ((const float4*)arow)[lane + 32*t];
            mx = fmaxf(mx, fmaxf(fmaxf(vv[t].x,vv[t].y), fmaxf(vv[t].z,vv[t].w)));
        }
        #pragma unroll
        for (int o = 16; o; o >>= 1) mx = fmaxf(mx, __shfl_xor_sync(~0u, mx, o));
        float s = 0.f;
        #pragma unroll
        for (int t = 0; t < 4; t++) {
            vv[t].x = fexp(vv[t].x - mx); vv[t].y = fexp(vv[t].y - mx);
            vv[t].z = fexp(vv[t].z - mx); vv[t].w = fexp(vv[t].w - mx);
            s += vv[t].x + vv[t].y + vv[t].z + vv[t].w;
            *(float4*)&sP[w][lane*4 + t*128] = vv[t];
        }
        #pragma unroll
        for (int o = 16; o; o >>= 1) s += __shfl_xor_sync(~0u, s, o);
        if (lane == 0) sInv[w] = 1.0f / s;
    }
    __syncthreads();

    // phase B: warp w handles j in [w*64, w*64+64); lane owns 2 cols; acc 8 rows
    float2 acc[8] = {};
    const float2* vp = (const float2*)&g_v[(b*NN + w*64)*256 + h*64 + lane*2];
    #pragma unroll 4
    for (int jj = 0; jj < 64; jj += 2) {
        float2 v0 = vp[(size_t)jj * 128];
        float2 v1 = vp[(size_t)(jj+1) * 128];
        #pragma unroll
        for (int i = 0; i < 8; i++) {
            float2 pp = *(const float2*)&sP[i][w*64 + jj];
            acc[i].x = fmaf(pp.x, v0.x, acc[i].x);
            acc[i].y = fmaf(pp.x, v0.y, acc[i].y);
            acc[i].x = fmaf(pp.y, v1.x, acc[i].x);
            acc[i].y = fmaf(pp.y, v1.y, acc[i].y);
        }
    }
    #pragma unroll
    for (int i = 0; i < 8; i++)
        *(float2*)&sRed[w][i][lane*2] = acc[i];
    __syncthreads();

    // phase C: reduce 8 warp-partials; thread -> (i = tid>>5, d = (tid*2)&63)
    int i = tid >> 5, d = (tid * 2) & 63;
    float sx = 0.f, sy = 0.f;
    #pragma unroll
    for (int ww = 0; ww < 8; ww++) {
        float2 t = *(const float2*)&sRed[ww][i][d];
        sx += t.x; sy += t.y;
    }
    float inv = sInv[i];
    *(float2*)&g_ctx[(b*NN + i0 + i)*256 + h*64 + d] = make_float2(sx*inv, sy*inv);
}

__global__ __launch_bounds__(256) void k_out(
    const float* __restrict__ Wo, const float* __restrict__ bo,
    float* __restrict__ out)
{
    gemm32x64(g_ctx, Wo, bo, out, blockIdx.y * 32, blockIdx.x * 64);
}

// ---------------- host: Chebyshev fit of -m*erfc(m/sqrt2), m in [0,6], deg 12 ----------------
static GCoef fit_gelu_poly() {
    const int DEG = 12, M = 64;
    double cc[DEG+1], fv[M];
    for (int j = 0; j < M; j++) {
        double xx = cos(M_PI * (j + 0.5) / M);
        double m = 3.0 * (xx + 1.0);
        fv[j] = -m * erfc(m * 0.7071067811865476);
    }
    for (int k = 0; k <= DEG; k++) {
        double s = 0;
        for (int j = 0; j < M; j++) s += fv[j] * cos(k * M_PI * (j + 0.5) / M);
        cc[k] = s * ((k == 0 ? 1.0 : 2.0) / M);
    }
    double mono[DEG+1] = {0}, Tm2[DEG+1] = {0}, Tm1[DEG+1] = {0}, Tk[DEG+1];
    Tm2[0] = 1.0; Tm1[1] = 1.0;
    mono[0] += cc[0];
    mono[1] += cc[1];
    for (int k = 2; k <= DEG; k++) {
        for (int i = 0; i <= DEG; i++) Tk[i] = -Tm2[i] + 2.0 * (i > 0 ? Tm1[i-1] : 0.0);
        for (int i = 0; i <= DEG; i++) mono[i] += cc[k] * Tk[i];
        for (int i = 0; i <= DEG; i++) { Tm2[i] = Tm1[i]; Tm1[i] = Tk[i]; }
    }
    GCoef g;
    for (int i = 0; i <= DEG; i++) g.c[i] = (float)mono[i];
    return g;
}

extern "C" void kernel_launch(void* const* d_in, const int* in_sizes, int n_in,
                              void* d_out, int out_size)
{
    const float* x   = (const float*)d_in[0];
    const int*   adj = (const int*)  d_in[1];
    const float* Wq  = (const float*)d_in[2];
    const float* bq  = (const float*)d_in[3];
    const float* Wk  = (const float*)d_in[4];
    const float* bk  = (const float*)d_in[5];
    const float* Wv  = (const float*)d_in[6];
    const float* bv  = (const float*)d_in[7];
    const float* Wo  = (const float*)d_in[8];
    const float* bo  = (const float*)d_in[9];
    const float* Wp1 = (const float*)d_in[10];
    const float* bp1 = (const float*)d_in[11];
    const float* Wp2 = (const float*)d_in[12];
    const float* bp2 = (const float*)d_in[13];
    float* out = (float*)d_out;

    GCoef co = fit_gelu_poly();

    dim3 g1(20, 32);
    k_proj<<<g1, 256>>>(x, Wq, bq, Wk, bk, Wv, bv, Wp1, bp1);

    dim3 g2(4, 64, 2);
    k_scores<<<g2, 256>>>(adj, Wp2, bp2, co);

    dim3 g4(64, 4, 2);
    k_av<<<g4, 256>>>();

    dim3 g5(4, 32);
    k_out<<<g5, 256>>>(Wo, bo, out);
}